// round 1
// baseline (speedup 1.0000x reference)
#include <cuda_runtime.h>
#include <cuda_bf16.h>
#include <math.h>

#define N_NODES 4096
#define FDIM    256
#define HEADS   4
#define DHEAD   64
#define ALPHA_F 0.2f
#define TILE_N  32
#define TILE_M  32

// Scratch (allocation-free rule: __device__ globals)
__device__ float g_h [N_NODES * FDIM];
__device__ float g_si[N_NODES * HEADS];
__device__ float g_sj[N_NODES * HEADS];

// ---------------------------------------------------------------------------
// Kernel 1: h = x @ W   (4096x256 @ 256x256, fp32, 64x64 tiles, 4x4/thread)
// ---------------------------------------------------------------------------
__global__ __launch_bounds__(256) void gemm_xw(const float* __restrict__ x,
                                               const float* __restrict__ W) {
    __shared__ float As[16][64];   // [k][m]
    __shared__ float Bs[16][64];   // [k][n]
    const int t  = threadIdx.x;
    const int tx = t & 15, ty = t >> 4;
    const int row0 = blockIdx.y * 64, col0 = blockIdx.x * 64;
    float acc[4][4] = {};
    for (int k0 = 0; k0 < FDIM; k0 += 16) {
        {
            int n = t >> 2, kq = (t & 3) * 4;
            float4 v = *(const float4*)&x[(size_t)(row0 + n) * FDIM + k0 + kq];
            As[kq + 0][n] = v.x; As[kq + 1][n] = v.y;
            As[kq + 2][n] = v.z; As[kq + 3][n] = v.w;
            int kk = t >> 4, c4 = (t & 15) * 4;
            *(float4*)&Bs[kk][c4] =
                *(const float4*)&W[(size_t)(k0 + kk) * FDIM + col0 + c4];
        }
        __syncthreads();
#pragma unroll
        for (int k = 0; k < 16; k++) {
            float4 a = *(float4*)&As[k][ty * 4];
            float4 b = *(float4*)&Bs[k][tx * 4];
            float av[4] = {a.x, a.y, a.z, a.w};
            float bv[4] = {b.x, b.y, b.z, b.w};
#pragma unroll
            for (int i = 0; i < 4; i++)
#pragma unroll
                for (int j = 0; j < 4; j++)
                    acc[i][j] = fmaf(av[i], bv[j], acc[i][j]);
        }
        __syncthreads();
    }
#pragma unroll
    for (int i = 0; i < 4; i++) {
        float4 o = make_float4(acc[i][0], acc[i][1], acc[i][2], acc[i][3]);
        *(float4*)&g_h[(size_t)(row0 + ty * 4 + i) * FDIM + col0 + tx * 4] = o;
    }
}

// ---------------------------------------------------------------------------
// Kernel 2: si[n,h] = h[n,h,:].a1 ; sj[n,h] = h[n,h,:].a2
// ---------------------------------------------------------------------------
__global__ __launch_bounds__(256) void compute_scores(const float* __restrict__ a) {
    const int n = blockIdx.x;
    const int t = threadIdx.x;
    float v  = g_h[(size_t)n * FDIM + t];
    float s1 = v * a[t & 63];
    float s2 = v * a[64 + (t & 63)];
#pragma unroll
    for (int o = 16; o; o >>= 1) {
        s1 += __shfl_xor_sync(0xffffffffu, s1, o);
        s2 += __shfl_xor_sync(0xffffffffu, s2, o);
    }
    __shared__ float w1[8], w2[8];
    if ((t & 31) == 0) { w1[t >> 5] = s1; w2[t >> 5] = s2; }
    __syncthreads();
    if (t < HEADS) {
        g_si[(size_t)n * HEADS + t] = w1[2 * t] + w1[2 * t + 1];
        g_sj[(size_t)n * HEADS + t] = w2[2 * t] + w2[2 * t + 1];
    }
}

// ---------------------------------------------------------------------------
// Kernel 3: masked-softmax attention + aggregation + LayerNorm, fused.
// One block owns TILE_N=32 rows (all 4 heads). Two-pass softmax:
//   pass1: rowmax[n,h] = lrelu(si + masked-max sj)  (monotonicity of lrelu)
//   pass2: stream m-tiles: p = exp(lrelu(si+sj)-rowmax) masked; acc += p*h
// then denom-normalize + LayerNorm in-block.
// ---------------------------------------------------------------------------
__global__ __launch_bounds__(256) void gat_main(const int*   __restrict__ adj,
                                                const float* __restrict__ gamma,
                                                const float* __restrict__ beta,
                                                float*       __restrict__ out) {
    extern __shared__ float smem[];
    float* h_sh    = smem;              // 32*256 = 8192 floats (reused as vbuf)
    float* p_sh    = smem + 8192;       // 32*4*32 = 4096 floats
    float* si_sh   = smem + 12288;      // 128
    float* rmax_sh = smem + 12416;      // 128
    float* den_sh  = smem + 12544;      // 128
    float* sj_t    = smem + 12672;      // 128
    float* stats   = smem + 12800;      // 64  (mu, rstd per row)

    const int t    = threadIdx.x;
    const int lane = t & 31, warp = t >> 5;
    const int n0   = blockIdx.x * TILE_N;

    if (t < TILE_N * HEADS) si_sh[t] = g_si[(size_t)n0 * HEADS + t];
    __syncthreads();

    // ---------------- pass 1: row maxima ----------------
    for (int n = warp; n < TILE_N; n += 8) {
        const int* arow = adj + (size_t)(n0 + n) * N_NODES;
        float m0 = -INFINITY, m1 = -INFINITY, m2 = -INFINITY, m3 = -INFINITY;
        for (int c = 0; c < N_NODES / 32; c++) {
            int m = c * 32 + lane;
            if (arow[m] > 0) {
                float4 s = *(const float4*)&g_sj[(size_t)m * HEADS];
                m0 = fmaxf(m0, s.x); m1 = fmaxf(m1, s.y);
                m2 = fmaxf(m2, s.z); m3 = fmaxf(m3, s.w);
            }
        }
#pragma unroll
        for (int o = 16; o; o >>= 1) {
            m0 = fmaxf(m0, __shfl_xor_sync(0xffffffffu, m0, o));
            m1 = fmaxf(m1, __shfl_xor_sync(0xffffffffu, m1, o));
            m2 = fmaxf(m2, __shfl_xor_sync(0xffffffffu, m2, o));
            m3 = fmaxf(m3, __shfl_xor_sync(0xffffffffu, m3, o));
        }
        if (lane == 0) {
            float mv[4] = {m0, m1, m2, m3};
#pragma unroll
            for (int h = 0; h < 4; h++) {
                float e = si_sh[n * 4 + h] + mv[h];
                rmax_sh[n * 4 + h] = e > 0.f ? e : ALPHA_F * e;
            }
        }
    }
    __syncthreads();

    // ---------------- pass 2: p + aggregation ----------------
    float acc[TILE_N];
#pragma unroll
    for (int i = 0; i < TILE_N; i++) acc[i] = 0.f;
    float dloc[4] = {0.f, 0.f, 0.f, 0.f};

    const int pn  = t >> 3;          // row this thread computes p for
    const int ml0 = (t & 7) * 4;     // its 4 m-columns within the tile
    const int hw  = t >> 6;          // head of this thread's feature column
    float rm[4], siv[4];
#pragma unroll
    for (int h = 0; h < 4; h++) {
        rm[h]  = rmax_sh[pn * 4 + h];
        siv[h] = si_sh[pn * 4 + h];
    }

    for (int tile = 0; tile < N_NODES / TILE_M; tile++) {
        const int m0 = tile * TILE_M;
        // stage h tile (32 x 256)
#pragma unroll 4
        for (int r = 0; r < TILE_M; r++)
            h_sh[r * FDIM + t] = g_h[(size_t)(m0 + r) * FDIM + t];
        if (t < TILE_M * HEADS) sj_t[t] = g_sj[(size_t)m0 * HEADS + t];
        __syncthreads();

        // compute p (each thread: 1 row x 4 m x 4 heads)
        int4 a4 = *(const int4*)&adj[(size_t)(n0 + pn) * N_NODES + m0 + ml0];
        int av[4] = {a4.x, a4.y, a4.z, a4.w};
        float pv[4][4];
#pragma unroll
        for (int q = 0; q < 4; q++) {
            int ml = ml0 + q;
#pragma unroll
            for (int h = 0; h < 4; h++) {
                float e = siv[h] + sj_t[ml * 4 + h];
                e = e > 0.f ? e : ALPHA_F * e;
                float p = (av[q] > 0) ? __expf(e - rm[h]) : 0.f;
                pv[h][q] = p;
                dloc[h] += p;
            }
        }
#pragma unroll
        for (int h = 0; h < 4; h++)
            *(float4*)&p_sh[(pn * 4 + h) * TILE_M + ml0] =
                make_float4(pv[h][0], pv[h][1], pv[h][2], pv[h][3]);
        __syncthreads();

        // acc[n] += p[n,hw,m] * h[m, f]   (p loads are warp-uniform -> bcast)
#pragma unroll
        for (int g = 0; g < TILE_M / 4; g++) {
            float hv0 = h_sh[(g * 4 + 0) * FDIM + t];
            float hv1 = h_sh[(g * 4 + 1) * FDIM + t];
            float hv2 = h_sh[(g * 4 + 2) * FDIM + t];
            float hv3 = h_sh[(g * 4 + 3) * FDIM + t];
#pragma unroll
            for (int nn = 0; nn < TILE_N; nn++) {
                float4 p4 = *(float4*)&p_sh[(nn * 4 + hw) * TILE_M + g * 4];
                acc[nn] = fmaf(p4.x, hv0, acc[nn]);
                acc[nn] = fmaf(p4.y, hv1, acc[nn]);
                acc[nn] = fmaf(p4.z, hv2, acc[nn]);
                acc[nn] = fmaf(p4.w, hv3, acc[nn]);
            }
        }
        __syncthreads();
    }

    // ---------------- denom reduce (8 lanes per row, within warp) ----------
#pragma unroll
    for (int h = 0; h < 4; h++) {
        dloc[h] += __shfl_xor_sync(0xffffffffu, dloc[h], 1);
        dloc[h] += __shfl_xor_sync(0xffffffffu, dloc[h], 2);
        dloc[h] += __shfl_xor_sync(0xffffffffu, dloc[h], 4);
    }
    if ((t & 7) == 0) {
#pragma unroll
        for (int h = 0; h < 4; h++)
            den_sh[pn * 4 + h] = fmaxf(dloc[h], 1e-30f);
    }
    __syncthreads();

    // ---------------- normalize into vbuf (reuse h_sh) ----------------
#pragma unroll
    for (int nn = 0; nn < TILE_N; nn++)
        h_sh[nn * FDIM + t] = acc[nn] / den_sh[nn * 4 + hw];
    __syncthreads();

    // ---------------- LayerNorm stats: warp w -> rows 4w..4w+3 -------------
    for (int r = 0; r < 4; r++) {
        int n = warp * 4 + r;
        float s = 0.f, s2 = 0.f;
#pragma unroll
        for (int k = 0; k < 8; k++) {
            float v = h_sh[n * FDIM + lane + 32 * k];
            s += v; s2 = fmaf(v, v, s2);
        }
#pragma unroll
        for (int o = 16; o; o >>= 1) {
            s  += __shfl_xor_sync(0xffffffffu, s,  o);
            s2 += __shfl_xor_sync(0xffffffffu, s2, o);
        }
        if (lane == 0) {
            float mu  = s * (1.f / FDIM);
            float var = s2 * (1.f / FDIM) - mu * mu;
            stats[n * 2]     = mu;
            stats[n * 2 + 1] = rsqrtf(var + 1e-5f);
        }
    }
    __syncthreads();

    float gm = gamma[t], bt = beta[t];
#pragma unroll
    for (int nn = 0; nn < TILE_N; nn++) {
        float v = h_sh[nn * FDIM + t];
        out[(size_t)(n0 + nn) * FDIM + t] =
            fmaf(gm * (v - stats[nn * 2]), stats[nn * 2 + 1], bt);
    }
}

// ---------------------------------------------------------------------------
static const int GAT_SMEM_BYTES = 12864 * 4;   // 51456 B dynamic

extern "C" void kernel_launch(void* const* d_in, const int* in_sizes, int n_in,
                              void* d_out, int out_size) {
    const float* x     = (const float*)d_in[0];
    const int*   adj   = (const int*)  d_in[1];
    const float* W     = (const float*)d_in[2];
    const float* a     = (const float*)d_in[3];
    const float* gamma = (const float*)d_in[4];
    const float* beta  = (const float*)d_in[5];
    float*       out   = (float*)d_out;

    cudaFuncSetAttribute(gat_main, cudaFuncAttributeMaxDynamicSharedMemorySize,
                         GAT_SMEM_BYTES);

    gemm_xw<<<dim3(FDIM / 64, N_NODES / 64), 256>>>(x, W);
    compute_scores<<<N_NODES, 256>>>(a);
    gat_main<<<N_NODES / TILE_N, 256, GAT_SMEM_BYTES>>>(adj, gamma, beta, out);
}

// round 2
// speedup vs baseline: 2.0329x; 2.0329x over previous
#include <cuda_runtime.h>
#include <cuda_bf16.h>
#include <math.h>

#define N_NODES 4096
#define FDIM    256
#define HEADS   4
#define ALPHA_F 0.2f
#define TILE_N  32
#define TILE_M  32

// Scratch (allocation-free rule: __device__ globals)
__device__ float g_h [N_NODES * FDIM];
__device__ float g_si[N_NODES * HEADS];
__device__ float g_sj[N_NODES * HEADS];

// ---------------- packed f32x2 helpers (Blackwell FFMA2) -------------------
__device__ __forceinline__ unsigned long long pk2(float x, float y) {
    unsigned long long r;
    asm("mov.b64 %0,{%1,%2};" : "=l"(r) : "f"(x), "f"(y));
    return r;
}
__device__ __forceinline__ float2 upk2(unsigned long long v) {
    float2 r;
    asm("mov.b64 {%0,%1},%2;" : "=f"(r.x), "=f"(r.y) : "l"(v));
    return r;
}
__device__ __forceinline__ void fma2(unsigned long long& d,
                                     unsigned long long a,
                                     unsigned long long b) {
    asm("fma.rn.f32x2 %0,%1,%2,%0;" : "+l"(d) : "l"(a), "l"(b));
}

// ---------------------------------------------------------------------------
// Kernel 1: h = x @ W  (fp32 64x64 tiles) + fused si/sj epilogue.
// Each block's 64-col tile is exactly one head (col0/64 == head), so the
// si/sj dot products over that head's 64 dims are fully block-local.
// ---------------------------------------------------------------------------
__global__ __launch_bounds__(256) void gemm_xw(const float* __restrict__ x,
                                               const float* __restrict__ W,
                                               const float* __restrict__ a) {
    __shared__ float As[16][64];   // [k][m]
    __shared__ float Bs[16][64];   // [k][n]
    const int t  = threadIdx.x;
    const int tx = t & 15, ty = t >> 4;
    const int row0 = blockIdx.y * 64, col0 = blockIdx.x * 64;
    const int head = blockIdx.x;                 // FDIM/64 == HEADS
    float acc[4][4] = {};
    for (int k0 = 0; k0 < FDIM; k0 += 16) {
        {
            int n = t >> 2, kq = (t & 3) * 4;
            float4 v = *(const float4*)&x[(size_t)(row0 + n) * FDIM + k0 + kq];
            As[kq + 0][n] = v.x; As[kq + 1][n] = v.y;
            As[kq + 2][n] = v.z; As[kq + 3][n] = v.w;
            int kk = t >> 4, c4 = (t & 15) * 4;
            *(float4*)&Bs[kk][c4] =
                *(const float4*)&W[(size_t)(k0 + kk) * FDIM + col0 + c4];
        }
        __syncthreads();
#pragma unroll
        for (int k = 0; k < 16; k++) {
            float4 av4 = *(float4*)&As[k][ty * 4];
            float4 bv4 = *(float4*)&Bs[k][tx * 4];
            float av[4] = {av4.x, av4.y, av4.z, av4.w};
            float bv[4] = {bv4.x, bv4.y, bv4.z, bv4.w};
#pragma unroll
            for (int i = 0; i < 4; i++)
#pragma unroll
                for (int j = 0; j < 4; j++)
                    acc[i][j] = fmaf(av[i], bv[j], acc[i][j]);
        }
        __syncthreads();
    }
    // write h tile
#pragma unroll
    for (int i = 0; i < 4; i++) {
        float4 o = make_float4(acc[i][0], acc[i][1], acc[i][2], acc[i][3]);
        *(float4*)&g_h[(size_t)(row0 + ty * 4 + i) * FDIM + col0 + tx * 4] = o;
    }
    // scores epilogue
    float a1v[4], a2v[4];
#pragma unroll
    for (int j = 0; j < 4; j++) {
        a1v[j] = a[tx * 4 + j];
        a2v[j] = a[64 + tx * 4 + j];
    }
#pragma unroll
    for (int i = 0; i < 4; i++) {
        float s1 = 0.f, s2 = 0.f;
#pragma unroll
        for (int j = 0; j < 4; j++) {
            s1 = fmaf(acc[i][j], a1v[j], s1);
            s2 = fmaf(acc[i][j], a2v[j], s2);
        }
#pragma unroll
        for (int o = 1; o < 16; o <<= 1) {
            s1 += __shfl_xor_sync(0xffffffffu, s1, o);
            s2 += __shfl_xor_sync(0xffffffffu, s2, o);
        }
        if (tx == 0) {
            int row = row0 + ty * 4 + i;
            g_si[(size_t)row * HEADS + head] = s1;
            g_sj[(size_t)row * HEADS + head] = s2;
        }
    }
}

// ---------------------------------------------------------------------------
// Kernel 2: fused masked-softmax attention + aggregation + LayerNorm.
// Block = 32 rows x all heads. Pass1: masked row maxima via monotone lrelu.
// Pass2: per 32-m tile, warps compute p into double-buffered p_sh[h][m][nn]
// (lane==nn -> conflict-free), then every thread aggregates its 2 adjacent
// features (same head) over 16 rows using packed fma.rn.f32x2, with h
// streamed straight from L2 in software-pipelined chunks. One barrier/tile.
// ---------------------------------------------------------------------------
__global__ __launch_bounds__(256, 1) void gat_main(const int*   __restrict__ adj,
                                                   const float* __restrict__ gamma,
                                                   const float* __restrict__ beta,
                                                   float*       __restrict__ out) {
    extern __shared__ float smem[];
    float* p_sh    = smem;          // 2*4*32*32 = 8192 floats ([buf][h][m][nn])
    float* si_sh   = smem + 8192;   // 128
    float* rmax_sh = smem + 8320;   // 128
    float* den_sh  = smem + 8448;   // 128
    float* stats   = smem + 8576;   // 64

    const int t    = threadIdx.x;
    const int lane = t & 31, warp = t >> 5;
    const int n0   = blockIdx.x * TILE_N;

    if (t < 128) {
        si_sh[t]  = g_si[(size_t)n0 * HEADS + t];
        den_sh[t] = 0.f;
    }
    __syncthreads();

    // ---------------- pass 1: row maxima ----------------
    for (int n = warp; n < TILE_N; n += 8) {
        const int* arow = adj + (size_t)(n0 + n) * N_NODES;
        float m0 = -INFINITY, m1 = -INFINITY, m2 = -INFINITY, m3 = -INFINITY;
        for (int c = 0; c < N_NODES / 32; c++) {
            int m = c * 32 + lane;
            if (arow[m] > 0) {
                float4 s = *(const float4*)&g_sj[(size_t)m * HEADS];
                m0 = fmaxf(m0, s.x); m1 = fmaxf(m1, s.y);
                m2 = fmaxf(m2, s.z); m3 = fmaxf(m3, s.w);
            }
        }
#pragma unroll
        for (int o = 16; o; o >>= 1) {
            m0 = fmaxf(m0, __shfl_xor_sync(0xffffffffu, m0, o));
            m1 = fmaxf(m1, __shfl_xor_sync(0xffffffffu, m1, o));
            m2 = fmaxf(m2, __shfl_xor_sync(0xffffffffu, m2, o));
            m3 = fmaxf(m3, __shfl_xor_sync(0xffffffffu, m3, o));
        }
        if (lane == 0) {
            float mv[4] = {m0, m1, m2, m3};
#pragma unroll
            for (int h = 0; h < 4; h++) {
                float e = si_sh[n * 4 + h] + mv[h];
                rmax_sh[n * 4 + h] = e > 0.f ? e : ALPHA_F * e;
            }
        }
    }
    __syncthreads();

    // ---------------- pass 2 setup ----------------
    // p-compute role: warp == m-quad index, lane == nn row
    const int nn_p = lane;
    const int ml0  = warp * 4;
    float rm_p[4], si_p[4];
#pragma unroll
    for (int h = 0; h < 4; h++) {
        rm_p[h] = rmax_sh[nn_p * 4 + h];
        si_p[h] = si_sh[nn_p * 4 + h];
    }
    // aggregation role: rowgroup (16 rows) x feature pair (same head)
    const int rg   = t >> 7;
    const int fp   = t & 127;
    const int head = fp >> 5;
    const int f0   = head * 64 + (fp & 31) * 2;
    const int nnb  = rg * 16;

    unsigned long long accA[8], accB[8];
#pragma unroll
    for (int i = 0; i < 8; i++) { accA[i] = 0ull; accB[i] = 0ull; }
    float dloc[4] = {0.f, 0.f, 0.f, 0.f};
    float2 hb[2][8];

    const float* hcol = g_h + f0;

    for (int tile = 0; tile < N_NODES / TILE_M; tile++) {
        const int m0  = tile * TILE_M;
        const int buf = tile & 1;
        // prefetch h chunk 0 (hides under p-compute + barrier)
#pragma unroll
        for (int i = 0; i < 8; i++)
            hb[0][i] = *(const float2*)&hcol[(size_t)(m0 + i) * FDIM];

        // ---- p compute ----
        float* pbase = p_sh + buf * 4096;
        const int4 a4 = *(const int4*)&adj[(size_t)(n0 + nn_p) * N_NODES + m0 + ml0];
        const int av[4] = {a4.x, a4.y, a4.z, a4.w};
#pragma unroll
        for (int q = 0; q < 4; q++) {
            float4 sj4 = *(const float4*)&g_sj[(size_t)(m0 + ml0 + q) * HEADS];
            float sv[4] = {sj4.x, sj4.y, sj4.z, sj4.w};
#pragma unroll
            for (int h = 0; h < 4; h++) {
                float e = si_p[h] + sv[h];
                e = e > 0.f ? e : ALPHA_F * e;
                float p = (av[q] > 0) ? __expf(e - rm_p[h]) : 0.f;
                dloc[h] += p;
                pbase[(h * 32 + ml0 + q) * 32 + nn_p] = p;
            }
        }
        __syncthreads();

        // ---- aggregation ----
        const float* pb = p_sh + buf * 4096 + head * 1024;   // [m][nn]
#pragma unroll
        for (int c = 0; c < 4; c++) {
            if (c < 3) {
#pragma unroll
                for (int i = 0; i < 8; i++)
                    hb[(c + 1) & 1][i] =
                        *(const float2*)&hcol[(size_t)(m0 + (c + 1) * 8 + i) * FDIM];
            }
#pragma unroll
            for (int i = 0; i < 8; i++) {
                const int m = c * 8 + i;
                float2 h2 = hb[c & 1][i];
                unsigned long long hd0 = pk2(h2.x, h2.x);
                unsigned long long hd1 = pk2(h2.y, h2.y);
                const ulonglong2* pr4 = (const ulonglong2*)&pb[m * 32 + nnb];
#pragma unroll
                for (int k = 0; k < 4; k++) {
                    ulonglong2 pv = pr4[k];
                    fma2(accA[2 * k],     pv.x, hd0);
                    fma2(accB[2 * k],     pv.x, hd1);
                    fma2(accA[2 * k + 1], pv.y, hd0);
                    fma2(accB[2 * k + 1], pv.y, hd1);
                }
            }
        }
        // single barrier per tile: next iter's p-compute targets buf^1;
        // writes to buf recur only after the *next* barrier -> safe.
    }

    // ---------------- denominators ----------------
#pragma unroll
    for (int h = 0; h < 4; h++)
        atomicAdd(&den_sh[nn_p * 4 + h], dloc[h]);
    __syncthreads();
    if (t < 128) den_sh[t] = 1.f / fmaxf(den_sh[t], 1e-30f);
    __syncthreads();

    // ---------------- normalize into vbuf (reuse p_sh: [32][256]) ---------
    float* vbuf = p_sh;
#pragma unroll
    for (int pr = 0; pr < 8; pr++) {
        int ne = nnb + 2 * pr, no = ne + 1;
        float2 va = upk2(accA[pr]);
        float2 vb = upk2(accB[pr]);
        float re = den_sh[ne * 4 + head];
        float ro = den_sh[no * 4 + head];
        *(float2*)&vbuf[ne * 256 + f0] = make_float2(va.x * re, vb.x * re);
        *(float2*)&vbuf[no * 256 + f0] = make_float2(va.y * ro, vb.y * ro);
    }
    __syncthreads();

    // ---------------- LayerNorm stats ----------------
    for (int r = 0; r < 4; r++) {
        int n = warp * 4 + r;
        float s = 0.f, s2 = 0.f;
#pragma unroll
        for (int k = 0; k < 8; k++) {
            float v = vbuf[n * 256 + lane + 32 * k];
            s += v; s2 = fmaf(v, v, s2);
        }
#pragma unroll
        for (int o = 16; o; o >>= 1) {
            s  += __shfl_xor_sync(0xffffffffu, s,  o);
            s2 += __shfl_xor_sync(0xffffffffu, s2, o);
        }
        if (lane == 0) {
            float mu  = s * (1.f / FDIM);
            float var = s2 * (1.f / FDIM) - mu * mu;
            stats[n * 2]     = mu;
            stats[n * 2 + 1] = rsqrtf(var + 1e-5f);
        }
    }
    __syncthreads();

    float gm = gamma[t], bt = beta[t];
#pragma unroll
    for (int nn = 0; nn < TILE_N; nn++) {
        float v = vbuf[nn * 256 + t];
        out[(size_t)(n0 + nn) * FDIM + t] =
            fmaf(gm * (v - stats[nn * 2]), stats[nn * 2 + 1], bt);
    }
}

// ---------------------------------------------------------------------------
static const int GAT_SMEM_BYTES = 8640 * 4;   // 34560 B dynamic

extern "C" void kernel_launch(void* const* d_in, const int* in_sizes, int n_in,
                              void* d_out, int out_size) {
    const float* x     = (const float*)d_in[0];
    const int*   adj   = (const int*)  d_in[1];
    const float* W     = (const float*)d_in[2];
    const float* a     = (const float*)d_in[3];
    const float* gamma = (const float*)d_in[4];
    const float* beta  = (const float*)d_in[5];
    float*       out   = (float*)d_out;

    cudaFuncSetAttribute(gat_main, cudaFuncAttributeMaxDynamicSharedMemorySize,
                         GAT_SMEM_BYTES);

    gemm_xw<<<dim3(FDIM / 64, N_NODES / 64), 256>>>(x, W, a);
    gat_main<<<N_NODES / TILE_N, 256, GAT_SMEM_BYTES>>>(adj, gamma, beta, out);
}